// round 2
// baseline (speedup 1.0000x reference)
#include <cuda_runtime.h>
#include <math.h>

#define M 4096
#define CN 64
#define BNEPS 1e-5

typedef unsigned long long u64;

// ---------------- packed f32x2 helpers ----------------------------------------
__device__ __forceinline__ u64 pk(float lo, float hi) {
    u64 r; asm("mov.b64 %0,{%1,%2};" : "=l"(r) : "f"(lo), "f"(hi)); return r;
}
__device__ __forceinline__ void upk(u64 v, float& lo, float& hi) {
    asm("mov.b64 {%0,%1},%2;" : "=f"(lo), "=f"(hi) : "l"(v));
}
__device__ __forceinline__ u64 ffma2(u64 a, u64 b, u64 c) {
    u64 d; asm("fma.rn.f32x2 %0,%1,%2,%3;" : "=l"(d) : "l"(a), "l"(b), "l"(c)); return d;
}
__device__ __forceinline__ u64 fadd2(u64 a, u64 b) {
    u64 d; asm("add.rn.f32x2 %0,%1,%2;" : "=l"(d) : "l"(a), "l"(b)); return d;
}
__device__ __forceinline__ u64 relu2(u64 v) {
    float a, b; upk(v, a, b); return pk(fmaxf(a, 0.f), fmaxf(b, 0.f));
}

// ---------------- scratch (device globals; no allocs allowed) ----------------
__device__ float g_table[5*16*64*16];                 // 320 KB
__device__ float g_bn0s1[CN], g_bn0s2[CN];
__device__ float g_bn1s[CN],  g_bn1q[CN];
__device__ float g_bn2s[CN],  g_bn2q[CN];
__device__ float g_scale0[CN], g_shift0[CN], g_u0[CN];
__device__ float g_base_r[CN*32];
__device__ float g_rc3[CN*32];
__device__ float g_scale1[CN], g_shift1[CN];
__device__ float g_rc4[CN*16];
__device__ float g_scale2[CN], g_shift2[CN];
__device__ float g_outconst[16];
__device__ float g_r3[(size_t)CN*4*32*M];             // 128 MB, layout [c][h][o][m]
__device__ float g_r4[(size_t)CN*4*16*M];             // 64 MB,  layout [c][h][o][m]

// ---------------- ktable: sparse-conv lookup table (+ accumulator zeroing) ----
// T[i][combo][c][h*4+w] = conv_w[c,i,r-h,s-w] if h<=r && w<=s else 0
__global__ void ktable(const float* __restrict__ conv_w) {
    int idx = blockIdx.x*blockDim.x + threadIdx.x;
    if (blockIdx.x == 0 && threadIdx.x < CN) {
        int t = threadIdx.x;
        g_bn0s1[t]=0.f; g_bn0s2[t]=0.f;
        g_bn1s[t]=0.f;  g_bn1q[t]=0.f;
        g_bn2s[t]=0.f;  g_bn2q[t]=0.f;
    }
    if (idx >= 5*16*64*16) return;
    int hw = idx & 15, c = (idx>>4)&63, combo = (idx>>10)&15, i = idx>>14;
    int h = hw>>2, w = hw&3, r = combo>>2, s = combo&3;
    float v = 0.f;
    if (h <= r && w <= s) v = conv_w[c*125 + i*25 + (r-h)*5 + (s-w)];
    g_table[idx] = v;
}

// Per-block shared slice of the table for channel c: stab[i*256 + combo*16 + k]
__device__ __forceinline__ void load_stab(float* stab, int c, int t, int nt) {
    for (int idx = t; idx < 1280; idx += nt) {
        int i = idx >> 8, rem = idx & 255;
        stab[idx] = g_table[(i*16 + (rem>>4))*1024 + c*16 + (rem&15)];
    }
}

__device__ __forceinline__ void compute_a_s(int m, const int* __restrict__ x,
                                            const float* __restrict__ stab, float* a) {
#pragma unroll
    for (int k = 0; k < 16; k++) a[k] = 0.f;
#pragma unroll
    for (int i = 0; i < 5; i++) {
        int r = x[m*10 + 2*i]     & 3;
        int s = x[m*10 + 2*i + 1] & 3;
        const float4* tp = reinterpret_cast<const float4*>(stab + i*256 + (r*4+s)*16);
        float4 t0 = tp[0], t1 = tp[1], t2 = tp[2], t3 = tp[3];
        a[0]+=t0.x; a[1]+=t0.y; a[2]+=t0.z; a[3]+=t0.w;
        a[4]+=t1.x; a[5]+=t1.y; a[6]+=t1.z; a[7]+=t1.w;
        a[8]+=t2.x; a[9]+=t2.y; a[10]+=t2.z; a[11]+=t2.w;
        a[12]+=t3.x; a[13]+=t3.y; a[14]+=t3.z; a[15]+=t3.w;
    }
}

// ---------------- k1: BN0 raw sums over the varying 4x4 region ----------------
__global__ void __launch_bounds__(128) k1(const int* __restrict__ x) {
    __shared__ __align__(16) float stab[1280];
    int c  = blockIdx.y;
    int t  = threadIdx.x;
    load_stab(stab, c, t, 128);
    __syncthreads();
    int mp = blockIdx.x*128 + t;
    float a0[16], a1[16];
    compute_a_s(2*mp,   x, stab, a0);
    compute_a_s(2*mp+1, x, stab, a1);
    float s = 0.f, q = 0.f;
#pragma unroll
    for (int k = 0; k < 16; k++) {
        s += a0[k] + a1[k];
        q += a0[k]*a0[k] + a1[k]*a1[k];
    }
    for (int off = 16; off; off >>= 1) {
        s += __shfl_down_sync(0xffffffffu, s, off);
        q += __shfl_down_sync(0xffffffffu, q, off);
    }
    __shared__ float ss[4], sq[4];
    int w = t >> 5, l = t & 31;
    if (!l) { ss[w] = s; sq[w] = q; }
    __syncthreads();
    if (t == 0) {
        atomicAdd(&g_bn0s1[c], ss[0]+ss[1]+ss[2]+ss[3]);
        atomicAdd(&g_bn0s2[c], sq[0]+sq[1]+sq[2]+sq[3]);
    }
}

// ---------------- k2: finalize BN0, const path through w_rank/w_h1 -----------
// 1024 threads: warp-per-channel reductions, smem-staged weights.
__global__ void __launch_bounds__(1024) k2(const float* __restrict__ conv_b,
                   const float* __restrict__ bn0_g, const float* __restrict__ bn0_b,
                   const float* __restrict__ w_rank, const float* __restrict__ b_rank,
                   const float* __restrict__ w_h1,  const float* __restrict__ b_h1) {
    __shared__ float shW4[32], shWall[32], su0[64];
    __shared__ float sh_rc2[2048];
    __shared__ float swh1s[1024];
    int t = threadIdx.x;
    if (t < 64) {
        double n0   = (double)M * 110.0;
        double mu_a = (double)g_bn0s1[t] / n0;
        double var  = (double)g_bn0s2[t] / n0 - mu_a*mu_a;
        double cb   = (double)conv_b[t];
        double mean = cb + mu_a;
        double sc   = (double)bn0_g[t] / sqrt(var + BNEPS);
        double sh   = (double)bn0_b[t] - mean*sc;
        g_scale0[t] = (float)sc;
        g_shift0[t] = (float)sh;
        float u0    = fmaxf((float)(cb*sc + sh), 0.f);
        g_u0[t]     = u0;
        su0[t]      = u0;
    }
    if (t < 32) {
        float w4 = 0.f, wall = 0.f;
        for (int w = 0; w < 10; w++) { float v = w_rank[t*10+w]; wall += v; if (w >= 4) w4 += v; }
        shW4[t] = w4; shWall[t] = wall;
    }
    swh1s[t] = w_h1[t];
    __syncthreads();
#pragma unroll
    for (int rep = 0; rep < 2; rep++) {
        int idx = t + rep*1024;
        int c = idx >> 5, o = idx & 31;
        float br = b_rank[o];
        g_base_r[idx] = su0[c]*shW4[o] + br;
        sh_rc2[idx]   = fmaxf(su0[c]*shWall[o] + br, 0.f);
    }
    __syncthreads();
#pragma unroll
    for (int rep = 0; rep < 2; rep++) {
        int idx = t + rep*1024;
        int c = idx >> 5, o = idx & 31;
        float acc = b_h1[o];
#pragma unroll
        for (int i = 0; i < 32; i++) acc += sh_rc2[c*32+i] * swh1s[o*32+i];
        g_rc3[idx] = acc;
        float s = acc, q = acc*acc;
        for (int off = 16; off; off >>= 1) {
            s += __shfl_down_sync(0xffffffffu, s, off);
            q += __shfl_down_sync(0xffffffffu, q, off);
        }
        if (o == 0) {                                 // one warp == one channel
            float k = (float)(M*7);
            g_bn1s[c] += k*s;                         // single writer, stream-ordered
            g_bn1q[c] += k*q;
        }
    }
}

// ---------------- k3: fused bn0+relu -> w_rank+relu -> w_h1 (f32x2 packed) ----
__global__ void __launch_bounds__(128) k3(const int* __restrict__ x,
                                          const float* __restrict__ conv_b,
                                          const float* __restrict__ w_rank,
                                          const float* __restrict__ w_h1,
                                          const float* __restrict__ b_h1) {
    __shared__ __align__(16) float stab[1280];
    __shared__ __align__(16) u64 swh1p[1024];         // duplicated-packed weights, 8 KB
    __shared__ u64 sw4p[128], sb1p[32], sbasep[32];
    __shared__ float red_s, red_q;
    int c = blockIdx.y, t = threadIdx.x;
    load_stab(stab, c, t, 128);
    for (int idx = t; idx < 1024; idx += 128) { float w = w_h1[idx]; swh1p[idx] = pk(w, w); }
    if (t < 32) {
        float b = b_h1[t];        sb1p[t]   = pk(b, b);
        float ba = g_base_r[c*32 + t]; sbasep[t] = pk(ba, ba);
#pragma unroll
        for (int w = 0; w < 4; w++) { float v = w_rank[t*10+w]; sw4p[t*4+w] = pk(v, v); }
    }
    if (t == 0) { red_s = 0.f; red_q = 0.f; }
    __syncthreads();

    int mp = blockIdx.x*128 + t;
    float sc0 = g_scale0[c];
    float pc0 = conv_b[c]*sc0 + g_shift0[c];
    float a0[16], a1[16];
    compute_a_s(2*mp,   x, stab, a0);
    compute_a_s(2*mp+1, x, stab, a1);
    u64 ap[16];
#pragma unroll
    for (int k = 0; k < 16; k++) {                    // bn0 + relu, pack sample pair
        ap[k] = pk(fmaxf(a0[k]*sc0 + pc0, 0.f), fmaxf(a1[k]*sc0 + pc0, 0.f));
    }
    u64 sp = 0, qp = 0;                               // 0 == packed {0.f,0.f}
#pragma unroll
    for (int h = 0; h < 4; h++) {
        u64 r2p[32];
#pragma unroll
        for (int o = 0; o < 32; o++) {                // w_rank stage + relu
            u64 acc = sbasep[o];
#pragma unroll
            for (int w = 0; w < 4; w++) acc = ffma2(ap[h*4+w], sw4p[o*4+w], acc);
            r2p[o] = relu2(acc);
        }
        for (int o = 0; o < 32; o++) {                // w_h1 stage
            u64 acc = sb1p[o];
            const ulonglong2* wp = reinterpret_cast<const ulonglong2*>(swh1p + o*32);
#pragma unroll
            for (int i = 0; i < 16; i++) {
                ulonglong2 w2 = wp[i];
                acc = ffma2(r2p[2*i],   w2.x, acc);
                acc = ffma2(r2p[2*i+1], w2.y, acc);
            }
            sp = fadd2(acc, sp);
            qp = ffma2(acc, acc, qp);
            *reinterpret_cast<u64*>(&g_r3[(size_t)((c*4+h)*32+o)*M + 2*mp]) = acc;
        }
    }
    float s0, s1, q0, q1;
    upk(sp, s0, s1); upk(qp, q0, q1);
    float s = s0 + s1, q = q0 + q1;
    for (int off = 16; off; off >>= 1) {
        s += __shfl_down_sync(0xffffffffu, s, off);
        q += __shfl_down_sync(0xffffffffu, q, off);
    }
    if ((t & 31) == 0) { atomicAdd(&red_s, s); atomicAdd(&red_q, q); }
    __syncthreads();
    if (t == 0) { atomicAdd(&g_bn1s[c], red_s); atomicAdd(&g_bn1q[c], red_q); }
}

// ---------------- k4: finalize BN1, const path through w_h2 -------------------
__global__ void __launch_bounds__(1024) k4(const float* __restrict__ bn1_g,
                   const float* __restrict__ bn1_b,
                   const float* __restrict__ w_h2,  const float* __restrict__ b_h2) {
    __shared__ float rc3bn[2048];
    __shared__ float swh2s[512];
    __shared__ float ssc[64], ssh[64];
    int t = threadIdx.x;
    if (t < 64) {
        double n1   = (double)M * 11.0 * 32.0;
        double mean = (double)g_bn1s[t] / n1;
        double var  = (double)g_bn1q[t] / n1 - mean*mean;
        double sc   = (double)bn1_g[t] / sqrt(var + BNEPS);
        double sh   = (double)bn1_b[t] - mean*sc;
        g_scale1[t] = (float)sc;  ssc[t] = (float)sc;
        g_shift1[t] = (float)sh;  ssh[t] = (float)sh;
    }
    if (t < 512) swh2s[t] = w_h2[t];
    __syncthreads();
#pragma unroll
    for (int rep = 0; rep < 2; rep++) {
        int idx = t + rep*1024;
        int c = idx >> 5;
        rc3bn[idx] = fmaxf(g_rc3[idx]*ssc[c] + ssh[c], 0.f);
    }
    __syncthreads();
    {
        int c = t >> 4, o = t & 15;                   // 1024 threads cover all (c,o)
        float acc = b_h2[o];
#pragma unroll
        for (int i = 0; i < 32; i++) acc += rc3bn[c*32+i] * swh2s[o*32+i];
        g_rc4[t] = acc;
        float s = acc, q = acc*acc;
        for (int off = 8; off; off >>= 1) {
            s += __shfl_down_sync(0xffffffffu, s, off, 16);
            q += __shfl_down_sync(0xffffffffu, q, off, 16);
        }
        if (o == 0) {
            float k = (float)(M*7);
            g_bn2s[c] += k*s;
            g_bn2q[c] += k*q;
        }
    }
}

// ---------------- k5: fused bn1+relu -> w_h2 (f32x2 packed), BN2 sums ---------
__global__ void __launch_bounds__(128) k5(const float* __restrict__ w_h2,
                                          const float* __restrict__ b_h2) {
    __shared__ __align__(16) u64 swh2p[512];          // 4 KB
    __shared__ u64 sb2p[16];
    __shared__ float red_s, red_q;
    int c = blockIdx.y, t = threadIdx.x;
    for (int idx = t; idx < 512; idx += 128) { float w = w_h2[idx]; swh2p[idx] = pk(w, w); }
    if (t < 16) { float b = b_h2[t]; sb2p[t] = pk(b, b); }
    if (t == 0) { red_s = 0.f; red_q = 0.f; }
    __syncthreads();

    int mp = blockIdx.x*128 + t;
    float sc1 = g_scale1[c], sf1 = g_shift1[c];
    u64 sc1p = pk(sc1, sc1), sf1p = pk(sf1, sf1);
    u64 sp = 0, qp = 0;
#pragma unroll
    for (int h = 0; h < 4; h++) {
        u64 yp[32];
#pragma unroll
        for (int i = 0; i < 32; i++) {
            u64 v = *reinterpret_cast<const u64*>(&g_r3[(size_t)((c*4+h)*32+i)*M + 2*mp]);
            yp[i] = relu2(ffma2(v, sc1p, sf1p));
        }
        for (int o = 0; o < 16; o++) {
            u64 acc = sb2p[o];
            const ulonglong2* wp = reinterpret_cast<const ulonglong2*>(swh2p + o*32);
#pragma unroll
            for (int i = 0; i < 16; i++) {
                ulonglong2 w2 = wp[i];
                acc = ffma2(yp[2*i],   w2.x, acc);
                acc = ffma2(yp[2*i+1], w2.y, acc);
            }
            sp = fadd2(acc, sp);
            qp = ffma2(acc, acc, qp);
            *reinterpret_cast<u64*>(&g_r4[(size_t)((c*4+h)*16+o)*M + 2*mp]) = acc;
        }
    }
    float s0, s1, q0, q1;
    upk(sp, s0, s1); upk(qp, q0, q1);
    float s = s0 + s1, q = q0 + q1;
    for (int off = 16; off; off >>= 1) {
        s += __shfl_down_sync(0xffffffffu, s, off);
        q += __shfl_down_sync(0xffffffffu, q, off);
    }
    if ((t & 31) == 0) { atomicAdd(&red_s, s); atomicAdd(&red_q, q); }
    __syncthreads();
    if (t == 0) { atomicAdd(&g_bn2s[c], red_s); atomicAdd(&g_bn2q[c], red_q); }
}

// ---------------- k6: finalize BN2, constant-row output contribution ----------
__global__ void k6(const float* __restrict__ bn2_g, const float* __restrict__ bn2_b,
                   const float* __restrict__ w_out, const float* __restrict__ b_out) {
    __shared__ float rc5[64*16];
    int t = threadIdx.x;                              // 288 = 9 warps
    if (t < 64) {
        double n2   = (double)M * 11.0 * 16.0;
        double mean = (double)g_bn2s[t] / n2;
        double var  = (double)g_bn2q[t] / n2 - mean*mean;
        double sc   = (double)bn2_g[t] / sqrt(var + BNEPS);
        double sh   = (double)bn2_b[t] - mean*sc;
        g_scale2[t] = (float)sc;
        g_shift2[t] = (float)sh;
    }
    __syncthreads();
    for (int idx = t; idx < 1024; idx += 288) {
        int c = idx >> 4;
        rc5[idx] = fmaxf(g_rc4[idx]*g_scale2[c] + g_shift2[c], 0.f);
    }
    __syncthreads();
    int j = t >> 5, lane = t & 31;
    if (j < 9) {
        float acc = 0.f;
        for (int p = lane; p < 1024; p += 32) {
            int c = p >> 4, o = p & 15;
            float ws = 0.f;
#pragma unroll
            for (int h = 4; h < 11; h++) ws += w_out[j*11264 + c*176 + h*16 + o];
            acc += rc5[p]*ws;
        }
        for (int off = 16; off; off >>= 1) acc += __shfl_down_sync(0xffffffffu, acc, off);
        if (!lane) g_outconst[j] = b_out[j] + acc;
    }
}

// ---------------- k6b: seed output with constant part -------------------------
__global__ void k6b(float* __restrict__ out) {
    int idx = blockIdx.x*256 + threadIdx.x;
    if (idx < M*9) out[idx] = g_outconst[idx % 9];
}

// ---------------- k7: varying-feature GEMM (bn2+relu fused, f32x2 packed) -----
__global__ void __launch_bounds__(256) k7(const float* __restrict__ w_out,
                                          float* __restrict__ out) {
    __shared__ u64 sw[9*64];                          // duplicated-packed, 4.5 KB
    int t = threadIdx.x;
    int warp = t >> 5, lane = t & 31;
    int mbase = blockIdx.x*512 + warp*64 + lane*2;    // gridDim.x = 8
    int c0 = blockIdx.y*2;                            // gridDim.y = 32 (2 channels each)
    u64 acc[9];
#pragma unroll
    for (int j = 0; j < 9; j++) acc[j] = 0;
    for (int cc = 0; cc < 2; cc++) {
        int c = c0 + cc;
        __syncthreads();
        for (int idx = t; idx < 576; idx += 256) {
            int j = idx / 64, qq = idx % 64;          // feature-within-channel (h*16+o)
            float w = w_out[j*11264 + c*176 + qq];
            sw[idx] = pk(w, w);
        }
        __syncthreads();
        float sc = g_scale2[c], sf = g_shift2[c];
        u64 scp = pk(sc, sc), sfp = pk(sf, sf);
        for (int qq = 0; qq < 64; qq++) {
            u64 v = *reinterpret_cast<const u64*>(&g_r4[(size_t)(c*64+qq)*M + mbase]);
            u64 y = relu2(ffma2(v, scp, sfp));
#pragma unroll
            for (int j = 0; j < 9; j++) acc[j] = ffma2(y, sw[j*64+qq], acc[j]);
        }
    }
#pragma unroll
    for (int j = 0; j < 9; j++) {
        float a0, a1;
        upk(acc[j], a0, a1);
        atomicAdd(&out[(size_t)mbase*9 + j],     a0);
        atomicAdd(&out[(size_t)(mbase+1)*9 + j], a1);
    }
}

// ---------------- launch ------------------------------------------------------
extern "C" void kernel_launch(void* const* d_in, const int* in_sizes, int n_in,
                              void* d_out, int out_size) {
    const int*   x      = (const int*)  d_in[0];
    const float* conv_w = (const float*)d_in[1];
    const float* conv_b = (const float*)d_in[2];
    const float* bn0_g  = (const float*)d_in[3];
    const float* bn0_b  = (const float*)d_in[4];
    const float* w_rank = (const float*)d_in[5];
    const float* b_rank = (const float*)d_in[6];
    const float* w_h1   = (const float*)d_in[7];
    const float* b_h1   = (const float*)d_in[8];
    const float* bn1_g  = (const float*)d_in[9];
    const float* bn1_b  = (const float*)d_in[10];
    const float* w_h2   = (const float*)d_in[11];
    const float* b_h2   = (const float*)d_in[12];
    const float* bn2_g  = (const float*)d_in[13];
    const float* bn2_b  = (const float*)d_in[14];
    const float* w_out  = (const float*)d_in[15];
    const float* b_out  = (const float*)d_in[16];
    float* out = (float*)d_out;

    ktable<<<80, 1024>>>(conv_w);
    k1<<<dim3(16, 64), 128>>>(x);
    k2<<<1, 1024>>>(conv_b, bn0_g, bn0_b, w_rank, b_rank, w_h1, b_h1);
    k3<<<dim3(16, 64), 128>>>(x, conv_b, w_rank, w_h1, b_h1);
    k4<<<1, 1024>>>(bn1_g, bn1_b, w_h2, b_h2);
    k5<<<dim3(16, 64), 128>>>(w_h2, b_h2);
    k6<<<1, 288>>>(bn2_g, bn2_b, w_out, b_out);
    k6b<<<144, 256>>>(out);
    k7<<<dim3(8, 32), 256>>>(w_out, out);
}

// round 3
// speedup vs baseline: 1.1739x; 1.1739x over previous
#include <cuda_runtime.h>
#include <math.h>

#define M 4096
#define CN 64
#define BNEPS 1e-5

typedef unsigned long long u64;

// ---------------- packed f32x2 helpers ----------------------------------------
__device__ __forceinline__ u64 pk(float lo, float hi) {
    u64 r; asm("mov.b64 %0,{%1,%2};" : "=l"(r) : "f"(lo), "f"(hi)); return r;
}
__device__ __forceinline__ void upk(u64 v, float& lo, float& hi) {
    asm("mov.b64 {%0,%1},%2;" : "=f"(lo), "=f"(hi) : "l"(v));
}
__device__ __forceinline__ u64 ffma2(u64 a, u64 b, u64 c) {
    u64 d; asm("fma.rn.f32x2 %0,%1,%2,%3;" : "=l"(d) : "l"(a), "l"(b), "l"(c)); return d;
}

// ---------------- scratch (device globals; no allocs allowed) ----------------
__device__ float g_table[5*16*64*16];                 // 320 KB
__device__ float g_bn0s1[CN], g_bn0s2[CN];
__device__ float g_bn1s[CN],  g_bn1q[CN];
__device__ float g_bn2s[CN],  g_bn2q[CN];
__device__ float g_scale0[CN], g_shift0[CN], g_u0[CN];
__device__ float g_base_r[CN*32];
__device__ float g_rc3[CN*32];
__device__ float g_scale1[CN], g_shift1[CN];
__device__ float g_rc4[CN*16];
__device__ float g_scale2[CN], g_shift2[CN];
__device__ float g_outconst[16];
__device__ float g_r3[(size_t)CN*4*32*M];             // 128 MB, layout [c][h][o][m]
__device__ float g_r4[(size_t)CN*4*16*M];             // 64 MB,  layout [c][h][o][m]

// ---------------- ktable: sparse-conv lookup table (+ accumulator zeroing) ----
__global__ void ktable(const float* __restrict__ conv_w) {
    int idx = blockIdx.x*blockDim.x + threadIdx.x;
    if (blockIdx.x == 0 && threadIdx.x < CN) {
        int t = threadIdx.x;
        g_bn0s1[t]=0.f; g_bn0s2[t]=0.f;
        g_bn1s[t]=0.f;  g_bn1q[t]=0.f;
        g_bn2s[t]=0.f;  g_bn2q[t]=0.f;
    }
    if (idx >= 5*16*64*16) return;
    int hw = idx & 15, c = (idx>>4)&63, combo = (idx>>10)&15, i = idx>>14;
    int h = hw>>2, w = hw&3, r = combo>>2, s = combo&3;
    float v = 0.f;
    if (h <= r && w <= s) v = conv_w[c*125 + i*25 + (r-h)*5 + (s-w)];
    g_table[idx] = v;
}

// Per-block shared slice of the table for channel c: stab[i*256 + combo*16 + k]
__device__ __forceinline__ void load_stab(float* stab, int c, int t, int nt) {
    for (int idx = t; idx < 1280; idx += nt) {
        int i = idx >> 8, rem = idx & 255;
        stab[idx] = g_table[(i*16 + (rem>>4))*1024 + c*16 + (rem&15)];
    }
}

__device__ __forceinline__ void compute_a_s(int m, const int* __restrict__ x,
                                            const float* __restrict__ stab, float* a) {
#pragma unroll
    for (int k = 0; k < 16; k++) a[k] = 0.f;
#pragma unroll
    for (int i = 0; i < 5; i++) {
        int r = x[m*10 + 2*i]     & 3;
        int s = x[m*10 + 2*i + 1] & 3;
        const float4* tp = reinterpret_cast<const float4*>(stab + i*256 + (r*4+s)*16);
        float4 t0 = tp[0], t1 = tp[1], t2 = tp[2], t3 = tp[3];
        a[0]+=t0.x; a[1]+=t0.y; a[2]+=t0.z; a[3]+=t0.w;
        a[4]+=t1.x; a[5]+=t1.y; a[6]+=t1.z; a[7]+=t1.w;
        a[8]+=t2.x; a[9]+=t2.y; a[10]+=t2.z; a[11]+=t2.w;
        a[12]+=t3.x; a[13]+=t3.y; a[14]+=t3.z; a[15]+=t3.w;
    }
}

// ---------------- k1: BN0 raw sums over the varying 4x4 region ----------------
__global__ void __launch_bounds__(256) k1(const int* __restrict__ x) {
    __shared__ __align__(16) float stab[1280];
    __shared__ float red_s, red_q;
    int c  = blockIdx.y;
    int t  = threadIdx.x;
    load_stab(stab, c, t, 256);
    if (t == 0) { red_s = 0.f; red_q = 0.f; }
    __syncthreads();
    int m = blockIdx.x*256 + t;
    float a[16];
    compute_a_s(m, x, stab, a);
    float s = 0.f, q = 0.f;
#pragma unroll
    for (int k = 0; k < 16; k++) { s += a[k]; q += a[k]*a[k]; }
    for (int off = 16; off; off >>= 1) {
        s += __shfl_down_sync(0xffffffffu, s, off);
        q += __shfl_down_sync(0xffffffffu, q, off);
    }
    if ((t & 31) == 0) { atomicAdd(&red_s, s); atomicAdd(&red_q, q); }
    __syncthreads();
    if (t == 0) {
        atomicAdd(&g_bn0s1[c], red_s);
        atomicAdd(&g_bn0s2[c], red_q);
    }
}

// ---------------- k2: finalize BN0, const path through w_rank/w_h1 -----------
__global__ void __launch_bounds__(1024) k2(const float* __restrict__ conv_b,
                   const float* __restrict__ bn0_g, const float* __restrict__ bn0_b,
                   const float* __restrict__ w_rank, const float* __restrict__ b_rank,
                   const float* __restrict__ w_h1,  const float* __restrict__ b_h1) {
    __shared__ float shW4[32], shWall[32], su0[64];
    __shared__ float sh_rc2[2048];
    __shared__ float swh1s[1024];
    int t = threadIdx.x;
    if (t < 64) {
        double n0   = (double)M * 110.0;
        double mu_a = (double)g_bn0s1[t] / n0;
        double var  = (double)g_bn0s2[t] / n0 - mu_a*mu_a;
        double cb   = (double)conv_b[t];
        double mean = cb + mu_a;
        double sc   = (double)bn0_g[t] / sqrt(var + BNEPS);
        double sh   = (double)bn0_b[t] - mean*sc;
        g_scale0[t] = (float)sc;
        g_shift0[t] = (float)sh;
        float u0    = fmaxf((float)(cb*sc + sh), 0.f);
        g_u0[t]     = u0;
        su0[t]      = u0;
    }
    if (t < 32) {
        float w4 = 0.f, wall = 0.f;
        for (int w = 0; w < 10; w++) { float v = w_rank[t*10+w]; wall += v; if (w >= 4) w4 += v; }
        shW4[t] = w4; shWall[t] = wall;
    }
    swh1s[t] = w_h1[t];
    __syncthreads();
#pragma unroll
    for (int rep = 0; rep < 2; rep++) {
        int idx = t + rep*1024;
        int c = idx >> 5, o = idx & 31;
        float br = b_rank[o];
        g_base_r[idx] = su0[c]*shW4[o] + br;
        sh_rc2[idx]   = fmaxf(su0[c]*shWall[o] + br, 0.f);
    }
    __syncthreads();
#pragma unroll
    for (int rep = 0; rep < 2; rep++) {
        int idx = t + rep*1024;
        int c = idx >> 5, o = idx & 31;
        float acc = b_h1[o];
#pragma unroll
        for (int i = 0; i < 32; i++) acc += sh_rc2[c*32+i] * swh1s[o*32+i];
        g_rc3[idx] = acc;
        float s = acc, q = acc*acc;
        for (int off = 16; off; off >>= 1) {
            s += __shfl_down_sync(0xffffffffu, s, off);
            q += __shfl_down_sync(0xffffffffu, q, off);
        }
        if (o == 0) {
            float k = (float)(M*7);
            g_bn1s[c] += k*s;
            g_bn1q[c] += k*q;
        }
    }
}

// ---------------- k3: fused bn0+relu -> w_rank+relu -> w_h1 -------------------
// One sample per thread; f32x2 packs ADJACENT reduction indices (i, i+1).
__global__ void __launch_bounds__(256, 3) k3(const int* __restrict__ x,
                                             const float* __restrict__ conv_b,
                                             const float* __restrict__ w_rank,
                                             const float* __restrict__ w_h1,
                                             const float* __restrict__ b_h1) {
    __shared__ __align__(16) float stab[1280];
    __shared__ __align__(16) u64 swh1p[512];          // [o][i2]: pk(w[o][2i], w[o][2i+1])
    __shared__ float sw4[128], sb1[32], sbase[32];
    __shared__ float red_s, red_q;
    int c = blockIdx.y, t = threadIdx.x;
    load_stab(stab, c, t, 256);
    for (int idx = t; idx < 512; idx += 256) {
        int o = idx >> 4, i2 = idx & 15;
        swh1p[idx] = pk(w_h1[o*32 + 2*i2], w_h1[o*32 + 2*i2 + 1]);
    }
    if (t < 32) {
        sb1[t]   = b_h1[t];
        sbase[t] = g_base_r[c*32 + t];
#pragma unroll
        for (int w = 0; w < 4; w++) sw4[t*4+w] = w_rank[t*10+w];
    }
    if (t == 0) { red_s = 0.f; red_q = 0.f; }
    __syncthreads();

    int m = blockIdx.x*256 + t;
    float sc0 = g_scale0[c];
    float pc0 = conv_b[c]*sc0 + g_shift0[c];
    float a[16];
    compute_a_s(m, x, stab, a);
#pragma unroll
    for (int k = 0; k < 16; k++) a[k] = fmaxf(a[k]*sc0 + pc0, 0.f);   // bn0 + relu

    float s = 0.f, q = 0.f;
#pragma unroll
    for (int h = 0; h < 4; h++) {
        float a0 = a[h*4+0], a1 = a[h*4+1], a2 = a[h*4+2], a3 = a[h*4+3];
        u64 r2p[16];
#pragma unroll
        for (int oo = 0; oo < 16; oo++) {             // w_rank stage + relu, pack pairs
            float e0 = sbase[2*oo],   e1 = sbase[2*oo+1];
            e0 += a0*sw4[(2*oo)*4+0];   e1 += a0*sw4[(2*oo+1)*4+0];
            e0 += a1*sw4[(2*oo)*4+1];   e1 += a1*sw4[(2*oo+1)*4+1];
            e0 += a2*sw4[(2*oo)*4+2];   e1 += a2*sw4[(2*oo+1)*4+2];
            e0 += a3*sw4[(2*oo)*4+3];   e1 += a3*sw4[(2*oo+1)*4+3];
            r2p[oo] = pk(fmaxf(e0, 0.f), fmaxf(e1, 0.f));
        }
        float* outp = &g_r3[(size_t)(c*4+h)*32*M + m];
#pragma unroll 4
        for (int o = 0; o < 32; o++) {                // w_h1 stage, SIMD dot-product
            u64 acc = pk(sb1[o], 0.f);
            const ulonglong2* wp = reinterpret_cast<const ulonglong2*>(swh1p + o*16);
#pragma unroll
            for (int i = 0; i < 8; i++) {
                ulonglong2 w2 = wp[i];
                acc = ffma2(r2p[2*i],   w2.x, acc);
                acc = ffma2(r2p[2*i+1], w2.y, acc);
            }
            float lo, hi; upk(acc, lo, hi);
            float v = lo + hi;
            s += v; q += v*v;
            outp[(size_t)o*M] = v;
        }
    }
    for (int off = 16; off; off >>= 1) {
        s += __shfl_down_sync(0xffffffffu, s, off);
        q += __shfl_down_sync(0xffffffffu, q, off);
    }
    if ((t & 31) == 0) { atomicAdd(&red_s, s); atomicAdd(&red_q, q); }
    __syncthreads();
    if (t == 0) { atomicAdd(&g_bn1s[c], red_s); atomicAdd(&g_bn1q[c], red_q); }
}

// ---------------- k4: finalize BN1, const path through w_h2 -------------------
__global__ void __launch_bounds__(1024) k4(const float* __restrict__ bn1_g,
                   const float* __restrict__ bn1_b,
                   const float* __restrict__ w_h2,  const float* __restrict__ b_h2) {
    __shared__ float rc3bn[2048];
    __shared__ float swh2s[512];
    __shared__ float ssc[64], ssh[64];
    int t = threadIdx.x;
    if (t < 64) {
        double n1   = (double)M * 11.0 * 32.0;
        double mean = (double)g_bn1s[t] / n1;
        double var  = (double)g_bn1q[t] / n1 - mean*mean;
        double sc   = (double)bn1_g[t] / sqrt(var + BNEPS);
        double sh   = (double)bn1_b[t] - mean*sc;
        g_scale1[t] = (float)sc;  ssc[t] = (float)sc;
        g_shift1[t] = (float)sh;  ssh[t] = (float)sh;
    }
    if (t < 512) swh2s[t] = w_h2[t];
    __syncthreads();
#pragma unroll
    for (int rep = 0; rep < 2; rep++) {
        int idx = t + rep*1024;
        int c = idx >> 5;
        rc3bn[idx] = fmaxf(g_rc3[idx]*ssc[c] + ssh[c], 0.f);
    }
    __syncthreads();
    {
        int c = t >> 4, o = t & 15;
        float acc = b_h2[o];
#pragma unroll
        for (int i = 0; i < 32; i++) acc += rc3bn[c*32+i] * swh2s[o*32+i];
        g_rc4[t] = acc;
        float s = acc, q = acc*acc;
        for (int off = 8; off; off >>= 1) {
            s += __shfl_down_sync(0xffffffffu, s, off, 16);
            q += __shfl_down_sync(0xffffffffu, q, off, 16);
        }
        if (o == 0) {
            float k = (float)(M*7);
            g_bn2s[c] += k*s;
            g_bn2q[c] += k*q;
        }
    }
}

// ---------------- k5: fused bn1+relu -> w_h2, BN2 sums ------------------------
// One sample per thread; f32x2 packs adjacent reduction indices.
__global__ void __launch_bounds__(256, 4) k5(const float* __restrict__ w_h2,
                                             const float* __restrict__ b_h2) {
    __shared__ __align__(16) u64 swh2p[256];          // [o][i2] packed pairs, 2 KB
    __shared__ float sb2[16];
    __shared__ float red_s, red_q;
    int c = blockIdx.y, t = threadIdx.x;
    if (t < 256) {
        int o = t >> 4, i2 = t & 15;
        swh2p[t] = pk(w_h2[o*32 + 2*i2], w_h2[o*32 + 2*i2 + 1]);
    }
    if (t < 16) sb2[t] = b_h2[t];
    if (t == 0) { red_s = 0.f; red_q = 0.f; }
    __syncthreads();

    int m = blockIdx.x*256 + t;
    float sc1 = g_scale1[c], sf1 = g_shift1[c];
    float s = 0.f, q = 0.f;
#pragma unroll
    for (int h = 0; h < 4; h++) {
        const float* inp = &g_r3[(size_t)(c*4+h)*32*M + m];
        u64 yp[16];
#pragma unroll
        for (int i2 = 0; i2 < 16; i2++) {
            float v0 = inp[(size_t)(2*i2)*M];
            float v1 = inp[(size_t)(2*i2+1)*M];
            yp[i2] = pk(fmaxf(v0*sc1 + sf1, 0.f), fmaxf(v1*sc1 + sf1, 0.f));
        }
        float* outp = &g_r4[(size_t)(c*4+h)*16*M + m];
#pragma unroll 4
        for (int o = 0; o < 16; o++) {
            u64 acc = pk(sb2[o], 0.f);
            const ulonglong2* wp = reinterpret_cast<const ulonglong2*>(swh2p + o*16);
#pragma unroll
            for (int i = 0; i < 8; i++) {
                ulonglong2 w2 = wp[i];
                acc = ffma2(yp[2*i],   w2.x, acc);
                acc = ffma2(yp[2*i+1], w2.y, acc);
            }
            float lo, hi; upk(acc, lo, hi);
            float v = lo + hi;
            s += v; q += v*v;
            outp[(size_t)o*M] = v;
        }
    }
    for (int off = 16; off; off >>= 1) {
        s += __shfl_down_sync(0xffffffffu, s, off);
        q += __shfl_down_sync(0xffffffffu, q, off);
    }
    if ((t & 31) == 0) { atomicAdd(&red_s, s); atomicAdd(&red_q, q); }
    __syncthreads();
    if (t == 0) { atomicAdd(&g_bn2s[c], red_s); atomicAdd(&g_bn2q[c], red_q); }
}

// ---------------- k6: finalize BN2, constant-row output contribution ----------
__global__ void k6(const float* __restrict__ bn2_g, const float* __restrict__ bn2_b,
                   const float* __restrict__ w_out, const float* __restrict__ b_out) {
    __shared__ float rc5[64*16];
    int t = threadIdx.x;                              // 288 = 9 warps
    if (t < 64) {
        double n2   = (double)M * 11.0 * 16.0;
        double mean = (double)g_bn2s[t] / n2;
        double var  = (double)g_bn2q[t] / n2 - mean*mean;
        double sc   = (double)bn2_g[t] / sqrt(var + BNEPS);
        double sh   = (double)bn2_b[t] - mean*sc;
        g_scale2[t] = (float)sc;
        g_shift2[t] = (float)sh;
    }
    __syncthreads();
    for (int idx = t; idx < 1024; idx += 288) {
        int c = idx >> 4;
        rc5[idx] = fmaxf(g_rc4[idx]*g_scale2[c] + g_shift2[c], 0.f);
    }
    __syncthreads();
    int j = t >> 5, lane = t & 31;
    if (j < 9) {
        float acc = 0.f;
        for (int p = lane; p < 1024; p += 32) {
            int c = p >> 4, o = p & 15;
            float ws = 0.f;
#pragma unroll
            for (int h = 4; h < 11; h++) ws += w_out[j*11264 + c*176 + h*16 + o];
            acc += rc5[p]*ws;
        }
        for (int off = 16; off; off >>= 1) acc += __shfl_down_sync(0xffffffffu, acc, off);
        if (!lane) g_outconst[j] = b_out[j] + acc;
    }
}

// ---------------- k6b: seed output with constant part -------------------------
__global__ void k6b(float* __restrict__ out) {
    int idx = blockIdx.x*256 + threadIdx.x;
    if (idx < M*9) out[idx] = g_outconst[idx % 9];
}

// ---------------- k7: varying-feature GEMM (bn2+relu fused, f32x2 packed) -----
__global__ void __launch_bounds__(256) k7(const float* __restrict__ w_out,
                                          float* __restrict__ out) {
    __shared__ u64 sw[9*64];                          // duplicated-packed, 4.5 KB
    int t = threadIdx.x;
    int warp = t >> 5, lane = t & 31;
    int mbase = blockIdx.x*512 + warp*64 + lane*2;
    int c0 = blockIdx.y*2;
    u64 acc[9];
#pragma unroll
    for (int j = 0; j < 9; j++) acc[j] = 0;
    for (int cc = 0; cc < 2; cc++) {
        int c = c0 + cc;
        __syncthreads();
        for (int idx = t; idx < 576; idx += 256) {
            int j = idx / 64, qq = idx % 64;
            float w = w_out[j*11264 + c*176 + qq];
            sw[idx] = pk(w, w);
        }
        __syncthreads();
        float sc = g_scale2[c], sf = g_shift2[c];
        u64 scp = pk(sc, sc), sfp = pk(sf, sf);
        for (int qq = 0; qq < 64; qq++) {
            u64 v = *reinterpret_cast<const u64*>(&g_r4[(size_t)(c*64+qq)*M + mbase]);
            u64 y = ffma2(v, scp, sfp);
            float y0, y1; upk(y, y0, y1);
            y = pk(fmaxf(y0, 0.f), fmaxf(y1, 0.f));
#pragma unroll
            for (int j = 0; j < 9; j++) acc[j] = ffma2(y, sw[j*64+qq], acc[j]);
        }
    }
#pragma unroll
    for (int j = 0; j < 9; j++) {
        float a0, a1;
        upk(acc[j], a0, a1);
        atomicAdd(&out[(size_t)mbase*9 + j],     a0);
        atomicAdd(&out[(size_t)(mbase+1)*9 + j], a1);
    }
}

// ---------------- launch ------------------------------------------------------
extern "C" void kernel_launch(void* const* d_in, const int* in_sizes, int n_in,
                              void* d_out, int out_size) {
    const int*   x      = (const int*)  d_in[0];
    const float* conv_w = (const float*)d_in[1];
    const float* conv_b = (const float*)d_in[2];
    const float* bn0_g  = (const float*)d_in[3];
    const float* bn0_b  = (const float*)d_in[4];
    const float* w_rank = (const float*)d_in[5];
    const float* b_rank = (const float*)d_in[6];
    const float* w_h1   = (const float*)d_in[7];
    const float* b_h1   = (const float*)d_in[8];
    const float* bn1_g  = (const float*)d_in[9];
    const float* bn1_b  = (const float*)d_in[10];
    const float* w_h2   = (const float*)d_in[11];
    const float* b_h2   = (const float*)d_in[12];
    const float* bn2_g  = (const float*)d_in[13];
    const float* bn2_b  = (const float*)d_in[14];
    const float* w_out  = (const float*)d_in[15];
    const float* b_out  = (const float*)d_in[16];
    float* out = (float*)d_out;

    ktable<<<80, 1024>>>(conv_w);
    k1<<<dim3(16, 64), 256>>>(x);
    k2<<<1, 1024>>>(conv_b, bn0_g, bn0_b, w_rank, b_rank, w_h1, b_h1);
    k3<<<dim3(16, 64), 256>>>(x, conv_b, w_rank, w_h1, b_h1);
    k4<<<1, 1024>>>(bn1_g, bn1_b, w_h2, b_h2);
    k5<<<dim3(16, 64), 256>>>(w_h2, b_h2);
    k6<<<1, 288>>>(bn2_g, bn2_b, w_out, b_out);
    k6b<<<144, 256>>>(out);
    k7<<<dim3(8, 32), 256>>>(w_out, out);
}

// round 4
// speedup vs baseline: 1.4696x; 1.2519x over previous
#include <cuda_runtime.h>
#include <math.h>

#define M 4096
#define CN 64
#define BNEPS 1e-5

typedef unsigned long long u64;

// ---------------- packed f32x2 helpers ----------------------------------------
__device__ __forceinline__ u64 pk(float lo, float hi) {
    u64 r; asm("mov.b64 %0,{%1,%2};" : "=l"(r) : "f"(lo), "f"(hi)); return r;
}
__device__ __forceinline__ void upk(u64 v, float& lo, float& hi) {
    asm("mov.b64 {%0,%1},%2;" : "=f"(lo), "=f"(hi) : "l"(v));
}
__device__ __forceinline__ u64 ffma2(u64 a, u64 b, u64 c) {
    u64 d; asm("fma.rn.f32x2 %0,%1,%2,%3;" : "=l"(d) : "l"(a), "l"(b), "l"(c)); return d;
}

// ---------------- scratch (device globals; no allocs allowed) ----------------
__device__ float g_table[5*16*64*16];                 // 320 KB
__device__ float g_bn0s1[CN], g_bn0s2[CN];
__device__ float g_bn1s[CN],  g_bn1q[CN];
__device__ float g_bn2s[CN],  g_bn2q[CN];
__device__ float g_scale0[CN], g_shift0[CN], g_u0[CN];
__device__ float g_base_r[CN*32];
__device__ float g_rc3[CN*32];
__device__ float g_scale1[CN], g_shift1[CN];
__device__ float g_rc4[CN*16];
__device__ float g_scale2[CN], g_shift2[CN];
__device__ float g_outconst[16];
__device__ float g_r3[(size_t)CN*4*32*M];             // 128 MB, layout [c][h][o][m]
__device__ float g_r4[(size_t)CN*4*16*M];             // 64 MB,  layout [c][h][o][m]

// ---------------- ktable: sparse-conv lookup table (+ accumulator zeroing) ----
__global__ void ktable(const float* __restrict__ conv_w) {
    int idx = blockIdx.x*blockDim.x + threadIdx.x;
    if (blockIdx.x == 0 && threadIdx.x < CN) {
        int t = threadIdx.x;
        g_bn0s1[t]=0.f; g_bn0s2[t]=0.f;
        g_bn1s[t]=0.f;  g_bn1q[t]=0.f;
        g_bn2s[t]=0.f;  g_bn2q[t]=0.f;
    }
    if (idx >= 5*16*64*16) return;
    int hw = idx & 15, c = (idx>>4)&63, combo = (idx>>10)&15, i = idx>>14;
    int h = hw>>2, w = hw&3, r = combo>>2, s = combo&3;
    float v = 0.f;
    if (h <= r && w <= s) v = conv_w[c*125 + i*25 + (r-h)*5 + (s-w)];
    g_table[idx] = v;
}

// Per-block shared slice of the table for channel c: stab[i*256 + combo*16 + k]
__device__ __forceinline__ void load_stab(float* stab, int c, int t, int nt) {
    for (int idx = t; idx < 1280; idx += nt) {
        int i = idx >> 8, rem = idx & 255;
        stab[idx] = g_table[(i*16 + (rem>>4))*1024 + c*16 + (rem&15)];
    }
}

__device__ __forceinline__ void compute_a_s(int m, const int* __restrict__ x,
                                            const float* __restrict__ stab, float* a) {
#pragma unroll
    for (int k = 0; k < 16; k++) a[k] = 0.f;
#pragma unroll
    for (int i = 0; i < 5; i++) {
        int r = x[m*10 + 2*i]     & 3;
        int s = x[m*10 + 2*i + 1] & 3;
        const float4* tp = reinterpret_cast<const float4*>(stab + i*256 + (r*4+s)*16);
        float4 t0 = tp[0], t1 = tp[1], t2 = tp[2], t3 = tp[3];
        a[0]+=t0.x; a[1]+=t0.y; a[2]+=t0.z; a[3]+=t0.w;
        a[4]+=t1.x; a[5]+=t1.y; a[6]+=t1.z; a[7]+=t1.w;
        a[8]+=t2.x; a[9]+=t2.y; a[10]+=t2.z; a[11]+=t2.w;
        a[12]+=t3.x; a[13]+=t3.y; a[14]+=t3.z; a[15]+=t3.w;
    }
}

// ---------------- k1: BN0 raw sums over the varying 4x4 region ----------------
__global__ void __launch_bounds__(256) k1(const int* __restrict__ x) {
    __shared__ __align__(16) float stab[1280];
    __shared__ float red_s, red_q;
    int c  = blockIdx.y;
    int t  = threadIdx.x;
    load_stab(stab, c, t, 256);
    if (t == 0) { red_s = 0.f; red_q = 0.f; }
    __syncthreads();
    int m = blockIdx.x*256 + t;
    float a[16];
    compute_a_s(m, x, stab, a);
    float s = 0.f, q = 0.f;
#pragma unroll
    for (int k = 0; k < 16; k++) { s += a[k]; q += a[k]*a[k]; }
    for (int off = 16; off; off >>= 1) {
        s += __shfl_down_sync(0xffffffffu, s, off);
        q += __shfl_down_sync(0xffffffffu, q, off);
    }
    if ((t & 31) == 0) { atomicAdd(&red_s, s); atomicAdd(&red_q, q); }
    __syncthreads();
    if (t == 0) {
        atomicAdd(&g_bn0s1[c], red_s);
        atomicAdd(&g_bn0s2[c], red_q);
    }
}

// ---------------- k2: finalize BN0, const path through w_rank/w_h1 -----------
__global__ void __launch_bounds__(1024) k2(const float* __restrict__ conv_b,
                   const float* __restrict__ bn0_g, const float* __restrict__ bn0_b,
                   const float* __restrict__ w_rank, const float* __restrict__ b_rank,
                   const float* __restrict__ w_h1,  const float* __restrict__ b_h1) {
    __shared__ float shW4[32], shWall[32], su0[64];
    __shared__ float sh_rc2[2048];
    __shared__ float swh1s[1024];
    int t = threadIdx.x;
    if (t < 64) {
        double n0   = (double)M * 110.0;
        double mu_a = (double)g_bn0s1[t] / n0;
        double var  = (double)g_bn0s2[t] / n0 - mu_a*mu_a;
        double cb   = (double)conv_b[t];
        double mean = cb + mu_a;
        double sc   = (double)bn0_g[t] / sqrt(var + BNEPS);
        double sh   = (double)bn0_b[t] - mean*sc;
        g_scale0[t] = (float)sc;
        g_shift0[t] = (float)sh;
        float u0    = fmaxf((float)(cb*sc + sh), 0.f);
        g_u0[t]     = u0;
        su0[t]      = u0;
    }
    if (t < 32) {
        float w4 = 0.f, wall = 0.f;
        for (int w = 0; w < 10; w++) { float v = w_rank[t*10+w]; wall += v; if (w >= 4) w4 += v; }
        shW4[t] = w4; shWall[t] = wall;
    }
    swh1s[t] = w_h1[t];
    __syncthreads();
#pragma unroll
    for (int rep = 0; rep < 2; rep++) {
        int idx = t + rep*1024;
        int c = idx >> 5, o = idx & 31;
        float br = b_rank[o];
        g_base_r[idx] = su0[c]*shW4[o] + br;
        sh_rc2[idx]   = fmaxf(su0[c]*shWall[o] + br, 0.f);
    }
    __syncthreads();
#pragma unroll
    for (int rep = 0; rep < 2; rep++) {
        int idx = t + rep*1024;
        int c = idx >> 5, o = idx & 31;
        float acc = b_h1[o];
#pragma unroll
        for (int i = 0; i < 32; i++) acc += sh_rc2[c*32+i] * swh1s[o*32+i];
        g_rc3[idx] = acc;
        float s = acc, q = acc*acc;
        for (int off = 16; off; off >>= 1) {
            s += __shfl_down_sync(0xffffffffu, s, off);
            q += __shfl_down_sync(0xffffffffu, q, off);
        }
        if (o == 0) {
            float k = (float)(M*7);
            g_bn1s[c] += k*s;
            g_bn1q[c] += k*q;
        }
    }
}

// ---------------- k3: fused bn0+relu -> w_rank+relu -> w_h1 -------------------
// Thread = (sample m, h-pair hp). r2 for BOTH h values lives in registers
// (i-adjacent f32x2 packed), so each weight LDS.128 feeds 4 FFMA2s.
__global__ void __launch_bounds__(256, 3) k3(const int* __restrict__ x,
                                             const float* __restrict__ conv_b,
                                             const float* __restrict__ w_rank,
                                             const float* __restrict__ w_h1,
                                             const float* __restrict__ b_h1) {
    __shared__ __align__(16) float stab[1280];
    __shared__ __align__(16) u64 swh1p[512];   // [o][i2]: pk(w[o][2i2], w[o][2i2+1])
    __shared__ __align__(16) u64 swr4p[64];    // [oo][w]: pk(w_rank[2oo][w], w_rank[2oo+1][w])
    __shared__ u64 sbasep[16];                 // pk(base[2oo], base[2oo+1])
    __shared__ u64 sb1p[32];                   // pk(b_h1[o], 0)
    __shared__ float red_s, red_q;
    int c = blockIdx.y, t = threadIdx.x;
    load_stab(stab, c, t, 256);
    for (int idx = t; idx < 512; idx += 256) {
        int o = idx >> 4, i2 = idx & 15;
        swh1p[idx] = pk(w_h1[o*32 + 2*i2], w_h1[o*32 + 2*i2 + 1]);
    }
    if (t < 64) {
        int oo = t >> 2, w = t & 3;
        swr4p[t] = pk(w_rank[(2*oo)*10 + w], w_rank[(2*oo+1)*10 + w]);
    }
    if (t < 32) sb1p[t] = pk(b_h1[t], 0.f);
    if (t < 16) sbasep[t] = pk(g_base_r[c*32 + 2*t], g_base_r[c*32 + 2*t + 1]);
    if (t == 0) { red_s = 0.f; red_q = 0.f; }
    __syncthreads();

    int hp = t >> 7;                       // h-pair: rows {2hp, 2hp+1}
    int m  = blockIdx.x*128 + (t & 127);
    float sc0 = g_scale0[c];
    float pc0 = conv_b[c]*sc0 + g_shift0[c];

    // conv rows 2hp, 2hp+1 only (8 values)
    float a8[8];
#pragma unroll
    for (int k = 0; k < 8; k++) a8[k] = 0.f;
    const int2* xp = reinterpret_cast<const int2*>(x + m*10);
#pragma unroll
    for (int i = 0; i < 5; i++) {
        int2 cd = xp[i];
        const float4* tp = reinterpret_cast<const float4*>(
            stab + i*256 + ((cd.x & 3)*4 + (cd.y & 3))*16 + hp*8);
        float4 t0 = tp[0], t1 = tp[1];
        a8[0]+=t0.x; a8[1]+=t0.y; a8[2]+=t0.z; a8[3]+=t0.w;
        a8[4]+=t1.x; a8[5]+=t1.y; a8[6]+=t1.z; a8[7]+=t1.w;
    }
#pragma unroll
    for (int k = 0; k < 8; k++) a8[k] = fmaxf(a8[k]*sc0 + pc0, 0.f);   // bn0 + relu

    // w_rank stage: r2 for both h, i-adjacent packed (output pairs of w_rank)
    u64 r2p0[16], r2p1[16];
#pragma unroll
    for (int hh = 0; hh < 2; hh++) {
        u64 ap0 = pk(a8[hh*4+0], a8[hh*4+0]);
        u64 ap1 = pk(a8[hh*4+1], a8[hh*4+1]);
        u64 ap2 = pk(a8[hh*4+2], a8[hh*4+2]);
        u64 ap3 = pk(a8[hh*4+3], a8[hh*4+3]);
#pragma unroll
        for (int oo = 0; oo < 16; oo++) {
            u64 e = sbasep[oo];
            const ulonglong2* wq = reinterpret_cast<const ulonglong2*>(swr4p + oo*4);
            ulonglong2 wa = wq[0], wb = wq[1];
            e = ffma2(ap0, wa.x, e);
            e = ffma2(ap1, wa.y, e);
            e = ffma2(ap2, wb.x, e);
            e = ffma2(ap3, wb.y, e);
            float e0, e1; upk(e, e0, e1);
            u64 r = pk(fmaxf(e0, 0.f), fmaxf(e1, 0.f));
            if (hh == 0) r2p0[oo] = r; else r2p1[oo] = r;
        }
    }

    // w_h1 stage: each weight load serves both h accumulators
    float s = 0.f, q = 0.f;
    size_t base0 = (size_t)((c*4 + 2*hp)*32)*M + m;   // row (c,h0,o=0)
#pragma unroll 4
    for (int o = 0; o < 32; o++) {
        const ulonglong2* wp = reinterpret_cast<const ulonglong2*>(swh1p + o*16);
        u64 acc0 = sb1p[o], acc1 = acc0;
#pragma unroll
        for (int i = 0; i < 8; i++) {
            ulonglong2 w2 = wp[i];
            acc0 = ffma2(r2p0[2*i],   w2.x, acc0);
            acc0 = ffma2(r2p0[2*i+1], w2.y, acc0);
            acc1 = ffma2(r2p1[2*i],   w2.x, acc1);
            acc1 = ffma2(r2p1[2*i+1], w2.y, acc1);
        }
        float l0, h0, l1, h1;
        upk(acc0, l0, h0); upk(acc1, l1, h1);
        float v0 = l0 + h0, v1 = l1 + h1;
        s += v0 + v1;
        q += v0*v0 + v1*v1;
        g_r3[base0 + (size_t)o*M]        = v0;
        g_r3[base0 + (size_t)(o + 32)*M] = v1;       // h0+1 row
    }
    for (int off = 16; off; off >>= 1) {
        s += __shfl_down_sync(0xffffffffu, s, off);
        q += __shfl_down_sync(0xffffffffu, q, off);
    }
    if ((t & 31) == 0) { atomicAdd(&red_s, s); atomicAdd(&red_q, q); }
    __syncthreads();
    if (t == 0) { atomicAdd(&g_bn1s[c], red_s); atomicAdd(&g_bn1q[c], red_q); }
}

// ---------------- k4: finalize BN1, const path through w_h2 -------------------
__global__ void __launch_bounds__(1024) k4(const float* __restrict__ bn1_g,
                   const float* __restrict__ bn1_b,
                   const float* __restrict__ w_h2,  const float* __restrict__ b_h2) {
    __shared__ float rc3bn[2048];
    __shared__ float swh2s[512];
    __shared__ float ssc[64], ssh[64];
    int t = threadIdx.x;
    if (t < 64) {
        double n1   = (double)M * 11.0 * 32.0;
        double mean = (double)g_bn1s[t] / n1;
        double var  = (double)g_bn1q[t] / n1 - mean*mean;
        double sc   = (double)bn1_g[t] / sqrt(var + BNEPS);
        double sh   = (double)bn1_b[t] - mean*sc;
        g_scale1[t] = (float)sc;  ssc[t] = (float)sc;
        g_shift1[t] = (float)sh;  ssh[t] = (float)sh;
    }
    if (t < 512) swh2s[t] = w_h2[t];
    __syncthreads();
#pragma unroll
    for (int rep = 0; rep < 2; rep++) {
        int idx = t + rep*1024;
        int c = idx >> 5;
        rc3bn[idx] = fmaxf(g_rc3[idx]*ssc[c] + ssh[c], 0.f);
    }
    __syncthreads();
    {
        int c = t >> 4, o = t & 15;
        float acc = b_h2[o];
#pragma unroll
        for (int i = 0; i < 32; i++) acc += rc3bn[c*32+i] * swh2s[o*32+i];
        g_rc4[t] = acc;
        float s = acc, q = acc*acc;
        for (int off = 8; off; off >>= 1) {
            s += __shfl_down_sync(0xffffffffu, s, off, 16);
            q += __shfl_down_sync(0xffffffffu, q, off, 16);
        }
        if (o == 0) {
            float k = (float)(M*7);
            g_bn2s[c] += k*s;
            g_bn2q[c] += k*q;
        }
    }
}

// ---------------- k5: fused bn1+relu -> w_h2, BN2 sums ------------------------
// Thread = (sample m, h-pair). Same weight-reuse structure as k3.
__global__ void __launch_bounds__(256, 3) k5(const float* __restrict__ w_h2,
                                             const float* __restrict__ b_h2) {
    __shared__ __align__(16) u64 swh2p[256];   // [o][i2] i-adjacent packed
    __shared__ u64 sb2p[16];
    __shared__ float red_s, red_q;
    int c = blockIdx.y, t = threadIdx.x;
    if (t < 256) {
        int o = t >> 4, i2 = t & 15;
        swh2p[t] = pk(w_h2[o*32 + 2*i2], w_h2[o*32 + 2*i2 + 1]);
    }
    if (t < 16) sb2p[t] = pk(b_h2[t], 0.f);
    if (t == 0) { red_s = 0.f; red_q = 0.f; }
    __syncthreads();

    int hp = t >> 7;
    int m  = blockIdx.x*128 + (t & 127);
    float sc1 = g_scale1[c], sf1 = g_shift1[c];

    // load + bn1 + relu for both h rows, i-adjacent packed
    u64 yp0[16], yp1[16];
    size_t rbase = (size_t)((c*4 + 2*hp)*32)*M + m;
#pragma unroll
    for (int i2 = 0; i2 < 16; i2++) {
        float v0 = g_r3[rbase + (size_t)(2*i2)*M];
        float v1 = g_r3[rbase + (size_t)(2*i2+1)*M];
        yp0[i2] = pk(fmaxf(v0*sc1 + sf1, 0.f), fmaxf(v1*sc1 + sf1, 0.f));
    }
#pragma unroll
    for (int i2 = 0; i2 < 16; i2++) {
        float v0 = g_r3[rbase + (size_t)(32 + 2*i2)*M];
        float v1 = g_r3[rbase + (size_t)(32 + 2*i2+1)*M];
        yp1[i2] = pk(fmaxf(v0*sc1 + sf1, 0.f), fmaxf(v1*sc1 + sf1, 0.f));
    }

    float s = 0.f, q = 0.f;
    size_t wbase = (size_t)((c*4 + 2*hp)*16)*M + m;
#pragma unroll 4
    for (int o = 0; o < 16; o++) {
        const ulonglong2* wp = reinterpret_cast<const ulonglong2*>(swh2p + o*16);
        u64 acc0 = sb2p[o], acc1 = acc0;
#pragma unroll
        for (int i = 0; i < 8; i++) {
            ulonglong2 w2 = wp[i];
            acc0 = ffma2(yp0[2*i],   w2.x, acc0);
            acc0 = ffma2(yp0[2*i+1], w2.y, acc0);
            acc1 = ffma2(yp1[2*i],   w2.x, acc1);
            acc1 = ffma2(yp1[2*i+1], w2.y, acc1);
        }
        float l0, h0, l1, h1;
        upk(acc0, l0, h0); upk(acc1, l1, h1);
        float v0 = l0 + h0, v1 = l1 + h1;
        s += v0 + v1;
        q += v0*v0 + v1*v1;
        g_r4[wbase + (size_t)o*M]        = v0;
        g_r4[wbase + (size_t)(o + 16)*M] = v1;
    }
    for (int off = 16; off; off >>= 1) {
        s += __shfl_down_sync(0xffffffffu, s, off);
        q += __shfl_down_sync(0xffffffffu, q, off);
    }
    if ((t & 31) == 0) { atomicAdd(&red_s, s); atomicAdd(&red_q, q); }
    __syncthreads();
    if (t == 0) { atomicAdd(&g_bn2s[c], red_s); atomicAdd(&g_bn2q[c], red_q); }
}

// ---------------- k6: finalize BN2, constant-row output contribution ----------
__global__ void k6(const float* __restrict__ bn2_g, const float* __restrict__ bn2_b,
                   const float* __restrict__ w_out, const float* __restrict__ b_out) {
    __shared__ float rc5[64*16];
    int t = threadIdx.x;                              // 288 = 9 warps
    if (t < 64) {
        double n2   = (double)M * 11.0 * 16.0;
        double mean = (double)g_bn2s[t] / n2;
        double var  = (double)g_bn2q[t] / n2 - mean*mean;
        double sc   = (double)bn2_g[t] / sqrt(var + BNEPS);
        double sh   = (double)bn2_b[t] - mean*sc;
        g_scale2[t] = (float)sc;
        g_shift2[t] = (float)sh;
    }
    __syncthreads();
    for (int idx = t; idx < 1024; idx += 288) {
        int c = idx >> 4;
        rc5[idx] = fmaxf(g_rc4[idx]*g_scale2[c] + g_shift2[c], 0.f);
    }
    __syncthreads();
    int j = t >> 5, lane = t & 31;
    if (j < 9) {
        float acc = 0.f;
        for (int p = lane; p < 1024; p += 32) {
            int c = p >> 4, o = p & 15;
            float ws = 0.f;
#pragma unroll
            for (int h = 4; h < 11; h++) ws += w_out[j*11264 + c*176 + h*16 + o];
            acc += rc5[p]*ws;
        }
        for (int off = 16; off; off >>= 1) acc += __shfl_down_sync(0xffffffffu, acc, off);
        if (!lane) g_outconst[j] = b_out[j] + acc;
    }
}

// ---------------- k6b: seed output with constant part -------------------------
__global__ void k6b(float* __restrict__ out) {
    int idx = blockIdx.x*256 + threadIdx.x;
    if (idx < M*9) out[idx] = g_outconst[idx % 9];
}

// ---------------- k7: varying-feature GEMM (bn2+relu fused, f32x2 packed) -----
__global__ void __launch_bounds__(256) k7(const float* __restrict__ w_out,
                                          float* __restrict__ out) {
    __shared__ u64 sw[9*64];                          // duplicated-packed, 4.5 KB
    int t = threadIdx.x;
    int warp = t >> 5, lane = t & 31;
    int mbase = blockIdx.x*512 + warp*64 + lane*2;
    int c0 = blockIdx.y*2;
    u64 acc[9];
#pragma unroll
    for (int j = 0; j < 9; j++) acc[j] = 0;
    for (int cc = 0; cc < 2; cc++) {
        int c = c0 + cc;
        __syncthreads();
        for (int idx = t; idx < 576; idx += 256) {
            int j = idx / 64, qq = idx % 64;
            float w = w_out[j*11264 + c*176 + qq];
            sw[idx] = pk(w, w);
        }
        __syncthreads();
        float sc = g_scale2[c], sf = g_shift2[c];
        u64 scp = pk(sc, sc), sfp = pk(sf, sf);
        for (int qq = 0; qq < 64; qq++) {
            u64 v = *reinterpret_cast<const u64*>(&g_r4[(size_t)(c*64+qq)*M + mbase]);
            u64 y = ffma2(v, scp, sfp);
            float y0, y1; upk(y, y0, y1);
            y = pk(fmaxf(y0, 0.f), fmaxf(y1, 0.f));
#pragma unroll
            for (int j = 0; j < 9; j++) acc[j] = ffma2(y, sw[j*64+qq], acc[j]);
        }
    }
#pragma unroll
    for (int j = 0; j < 9; j++) {
        float a0, a1;
        upk(acc[j], a0, a1);
        atomicAdd(&out[(size_t)mbase*9 + j],     a0);
        atomicAdd(&out[(size_t)(mbase+1)*9 + j], a1);
    }
}

// ---------------- launch ------------------------------------------------------
extern "C" void kernel_launch(void* const* d_in, const int* in_sizes, int n_in,
                              void* d_out, int out_size) {
    const int*   x      = (const int*)  d_in[0];
    const float* conv_w = (const float*)d_in[1];
    const float* conv_b = (const float*)d_in[2];
    const float* bn0_g  = (const float*)d_in[3];
    const float* bn0_b  = (const float*)d_in[4];
    const float* w_rank = (const float*)d_in[5];
    const float* b_rank = (const float*)d_in[6];
    const float* w_h1   = (const float*)d_in[7];
    const float* b_h1   = (const float*)d_in[8];
    const float* bn1_g  = (const float*)d_in[9];
    const float* bn1_b  = (const float*)d_in[10];
    const float* w_h2   = (const float*)d_in[11];
    const float* b_h2   = (const float*)d_in[12];
    const float* bn2_g  = (const float*)d_in[13];
    const float* bn2_b  = (const float*)d_in[14];
    const float* w_out  = (const float*)d_in[15];
    const float* b_out  = (const float*)d_in[16];
    float* out = (float*)d_out;

    ktable<<<80, 1024>>>(conv_w);
    k1<<<dim3(16, 64), 256>>>(x);
    k2<<<1, 1024>>>(conv_b, bn0_g, bn0_b, w_rank, b_rank, w_h1, b_h1);
    k3<<<dim3(32, 64), 256>>>(x, conv_b, w_rank, w_h1, b_h1);
    k4<<<1, 1024>>>(bn1_g, bn1_b, w_h2, b_h2);
    k5<<<dim3(32, 64), 256>>>(w_h2, b_h2);
    k6<<<1, 288>>>(bn2_g, bn2_b, w_out, b_out);
    k6b<<<144, 256>>>(out);
    k7<<<dim3(8, 32), 256>>>(w_out, out);
}